// round 5
// baseline (speedup 1.0000x reference)
#include <cuda_runtime.h>

#define N_FULL 50000
#define NLAT 10
#define MU 32
#define BATCH 8
#define TILE 16
#define ENC_CHUNKS 25
#define ENC_VPC 500         // float4 per chunk (25*500 = 12500 = N/4)
#define ENC_BLOCKS (ENC_CHUNKS * BATCH)     // 200
#define PREP_BLOCKS ((N_FULL + 255) / 256)  // 196

// Scratch (allocation-free rule: __device__ globals)
__device__ float  g_part[ENC_CHUNKS * BATCH * NLAT];  // [chunk][b*10+i] partial dots
__device__ float4 g_dect[N_FULL * 4];   // [node][4 x float4]: 10 decoder vals + pad

// ---------------------------------------------------------------------------
// Kernel 1 (fused): blocks [0,200) encode split-K partials (no atomics);
// blocks [200,396) transpose decoder into g_dect.
// ---------------------------------------------------------------------------
__global__ __launch_bounds__(256)
void encprep_kernel(const float* __restrict__ x,
                    const float* __restrict__ ew,
                    const float* __restrict__ dec) {
    int bid = blockIdx.x;
    int tid = threadIdx.x;

    if (bid < ENC_BLOCKS) {
        // ---- encode partial: g_part[chunk][b,i] = x[b,chunk] . enc_w[i,chunk]
        int b     = bid / ENC_CHUNKS;
        int chunk = bid % ENC_CHUNKS;
        int c0    = chunk * ENC_VPC;
        int t0 = tid, t1 = tid + 256;

        const float4* xv = (const float4*)(x + (size_t)b * N_FULL) + c0;
        float4 xa = xv[t0];
        float4 xb = (t1 < ENC_VPC) ? xv[t1] : make_float4(0.f, 0.f, 0.f, 0.f);

        float acc[NLAT];
        #pragma unroll
        for (int i = 0; i < NLAT; i++) {
            const float4* wv = (const float4*)(ew + (size_t)i * N_FULL) + c0;
            float4 wa = wv[t0];
            float4 wb = (t1 < ENC_VPC) ? wv[t1] : make_float4(0.f, 0.f, 0.f, 0.f);
            float s;
            s = xa.x * wa.x;
            s = fmaf(xa.y, wa.y, s);
            s = fmaf(xa.z, wa.z, s);
            s = fmaf(xa.w, wa.w, s);
            s = fmaf(xb.x, wb.x, s);
            s = fmaf(xb.y, wb.y, s);
            s = fmaf(xb.z, wb.z, s);
            s = fmaf(xb.w, wb.w, s);
            acc[i] = s;
        }

        __shared__ float red[8][NLAT];
        #pragma unroll
        for (int i = 0; i < NLAT; i++) {
            float s = acc[i];
            #pragma unroll
            for (int o = 16; o; o >>= 1) s += __shfl_down_sync(0xffffffffu, s, o);
            if ((tid & 31) == 0) red[tid >> 5][i] = s;
        }
        __syncthreads();
        if (tid < NLAT) {
            float s = 0.f;
            #pragma unroll
            for (int w = 0; w < 8; w++) s += red[w][tid];
            g_part[chunk * (BATCH * NLAT) + b * NLAT + tid] = s;
        }
    } else {
        // ---- prep: transpose decoder [10,N] -> g_dect [N][16] ----
        int j = (bid - ENC_BLOCKS) * 256 + tid;
        if (j >= N_FULL) return;
        float d[NLAT];
        #pragma unroll
        for (int i = 0; i < NLAT; i++) d[i] = dec[(size_t)i * N_FULL + j];
        g_dect[j * 4 + 0] = make_float4(d[0], d[1], d[2], d[3]);
        g_dect[j * 4 + 1] = make_float4(d[4], d[5], d[6], d[7]);
        g_dect[j * 4 + 2] = make_float4(d[8], d[9], 0.f, 0.f);
    }
}

// ---------------------------------------------------------------------------
// Kernel 2: main. Per block: TILE=16 nodes, 256 threads.
//   E: reduce encode partials (80 threads x 25 coalesced L2 loads + bias)
//   A: stage neighbour indices; issue coalesced bw-tile loads into smem
//   B: cooperative gather — 3 lanes share one 64B decoder row (1 L1 line)
//   C: prefix sums over m:  P0[m]=sum d,  P2[m]=sum d*m^2   (160 rows)
//   D: per (node,b,i-half): w from smem bw tile; closed-form window via K
// ---------------------------------------------------------------------------
__global__ __launch_bounds__(256)
void main_kernel(const float* __restrict__ bw,
                 const int*  __restrict__ nb,
                 const float* __restrict__ eb,
                 float*      __restrict__ out) {
    __shared__ float enc_s[BATCH * NLAT];
    __shared__ int   nbs[TILE * MU];          // 2KB; reused as float[256] for D-reduce
    __shared__ float bws[NLAT * NLAT * TILE]; // 6.4KB: [i*10+k][pl]
    __shared__ float P0s[TILE * NLAT * 33];   // [pl][i][m], stride 33
    __shared__ float P2s[TILE * NLAT * 33];

    int tid = threadIdx.x;
    int p0  = blockIdx.x * TILE;

    // ---- Phase E: per-block encode reduction ----
    if (tid < BATCH * NLAT) {
        float s = __ldg(&eb[tid - (tid / NLAT) * NLAT]);
        #pragma unroll
        for (int c = 0; c < ENC_CHUNKS; c++)
            s += g_part[c * (BATCH * NLAT) + tid];
        enc_s[tid] = s;
    }

    // ---- Phase A: stage indices (512 = 2 per thread) ----
    nbs[tid]       = __ldg(&nb[(size_t)p0 * MU + tid]);
    nbs[tid + 256] = __ldg(&nb[(size_t)p0 * MU + tid + 256]);

    // ---- bw tile: 100 rows x 16 nodes, 64B-coalesced ----
    #pragma unroll
    for (int it = 0; it < 7; it++) {
        int t = it * 256 + tid;
        if (t < NLAT * NLAT * TILE) {
            int ik = t >> 4, pl = t & 15;
            bws[t] = __ldg(&bw[(size_t)ik * N_FULL + p0 + pl]);
        }
    }
    __syncthreads();

    // ---- Phase B: cooperative gather (3 lanes per index -> 1 line) ----
    #pragma unroll
    for (int it = 0; it < TILE * MU * 3 / 256; it++) {
        int t = it * 256 + tid;
        int s = t / 3;                 // index id (0..511)
        int chunk = t - s * 3;         // 0,1,2
        int j = nbs[s];
        float4 v = g_dect[j * 4 + chunk];
        int base = (s >> 5) * (NLAT * 33) + (s & 31) + chunk * 132;
        P0s[base]      = v.x;
        P0s[base + 33] = v.y;
        if (chunk != 2) {
            P0s[base + 66] = v.z;
            P0s[base + 99] = v.w;
        }
    }
    __syncthreads();

    // ---- Phase C: in-place inclusive prefix sums over m (160 rows) ----
    if (tid < TILE * NLAT) {
        int base = tid * 33;
        float s0 = 0.f, s2 = 0.f;
        #pragma unroll
        for (int m = 0; m < MU; m++) {
            float g = P0s[base + m];
            s0 += g;
            s2 = fmaf(g, (float)(m * m), s2);
            P0s[base + m] = s0;
            P2s[base + m] = s2;
        }
    }
    __syncthreads();

    // ---- Phase D: 256 threads = 16 nodes x 8 b x 2 i-halves ----
    float* redf = (float*)nbs;
    {
        int b    = tid & 7;
        int pl   = (tid >> 3) & 15;
        int half = tid >> 7;
        float eb_[NLAT];
        #pragma unroll
        for (int k = 0; k < NLAT; k++) eb_[k] = enc_s[b * NLAT + k];

        float acc = 0.f;
        #pragma unroll
        for (int ii = 0; ii < 5; ii++) {
            int i = half * 5 + ii;
            float t = 0.f;
            #pragma unroll
            for (int k = 0; k < NLAT; k++)
                t = fmaf(eb_[k], bws[(i * NLAT + k) * TILE + pl], t);
            float w = 1.f / (1.f + __expf(-t));
            float u = fmaxf(32.f * w, 1e-6f);      // 32*w (window cutoff)
            float cinv = __fdividef(1.f, u * u);   // 1/(32w)^2
            int K = min(MU, (int)u + 1);           // #window terms
            float S2K = (float)((K - 1) * K * (2 * K - 1)) * (1.f / 6.f);
            int idx = (pl * NLAT + i) * 33 + (K - 1);
            float P0 = P0s[idx];
            float P2 = P2s[idx];
            float norm = (float)K - cinv * S2K;
            float sm = __fdividef(P0 - cinv * P2, norm);
            acc = fmaf(eb_[i], sm, acc);
        }
        redf[tid] = acc;
    }
    __syncthreads();
    if (tid < 128) {
        int b  = tid & 7;
        int pl = tid >> 3;
        out[(size_t)b * N_FULL + p0 + pl] = redf[tid] + redf[tid + 128];
    }
}

// ---------------------------------------------------------------------------
extern "C" void kernel_launch(void* const* d_in, const int* in_sizes, int n_in,
                              void* d_out, int out_size) {
    const float* x   = (const float*)d_in[0];
    const float* ew  = (const float*)d_in[1];
    const float* ebv = (const float*)d_in[2];
    const float* dec = (const float*)d_in[3];
    const float* bw  = (const float*)d_in[4];
    const int*   nb  = (const int*)d_in[5];
    float* out = (float*)d_out;

    encprep_kernel<<<ENC_BLOCKS + PREP_BLOCKS, 256>>>(x, ew, dec);
    main_kernel<<<N_FULL / TILE, 256>>>(bw, nb, ebv, out);
}

// round 6
// speedup vs baseline: 1.0051x; 1.0051x over previous
#include <cuda_runtime.h>

#define N_FULL 50000
#define NLAT 10
#define MU 32
#define BATCH 8
#define TILE 16
#define ENC_CHUNKS 25
#define ENC_VPC 500         // float4 per chunk (25*500 = 12500 = N/4)
#define ENC_BLOCKS (ENC_CHUNKS * BATCH)     // 200
#define PREP_BLOCKS ((N_FULL + 255) / 256)  // 196

// Scratch (allocation-free rule: __device__ globals)
__device__ float  g_part[ENC_CHUNKS * BATCH * NLAT];  // [chunk][b*10+i] partial dots
__device__ float4 g_dect[N_FULL * 4];   // [node][4 x float4]: 10 decoder vals + pad

// ---------------------------------------------------------------------------
// Kernel 1 (fused): blocks [0,200) encode split-K partials (no atomics);
// blocks [200,396) transpose decoder into g_dect.
// ---------------------------------------------------------------------------
__global__ __launch_bounds__(256)
void encprep_kernel(const float* __restrict__ x,
                    const float* __restrict__ ew,
                    const float* __restrict__ dec) {
    int bid = blockIdx.x;
    int tid = threadIdx.x;

    if (bid < ENC_BLOCKS) {
        int b     = bid / ENC_CHUNKS;
        int chunk = bid % ENC_CHUNKS;
        int c0    = chunk * ENC_VPC;
        int t0 = tid, t1 = tid + 256;

        const float4* xv = (const float4*)(x + (size_t)b * N_FULL) + c0;
        float4 xa = xv[t0];
        float4 xb = (t1 < ENC_VPC) ? xv[t1] : make_float4(0.f, 0.f, 0.f, 0.f);

        float acc[NLAT];
        #pragma unroll
        for (int i = 0; i < NLAT; i++) {
            const float4* wv = (const float4*)(ew + (size_t)i * N_FULL) + c0;
            float4 wa = wv[t0];
            float4 wb = (t1 < ENC_VPC) ? wv[t1] : make_float4(0.f, 0.f, 0.f, 0.f);
            float s;
            s = xa.x * wa.x;
            s = fmaf(xa.y, wa.y, s);
            s = fmaf(xa.z, wa.z, s);
            s = fmaf(xa.w, wa.w, s);
            s = fmaf(xb.x, wb.x, s);
            s = fmaf(xb.y, wb.y, s);
            s = fmaf(xb.z, wb.z, s);
            s = fmaf(xb.w, wb.w, s);
            acc[i] = s;
        }

        __shared__ float red[8][NLAT];
        #pragma unroll
        for (int i = 0; i < NLAT; i++) {
            float s = acc[i];
            #pragma unroll
            for (int o = 16; o; o >>= 1) s += __shfl_down_sync(0xffffffffu, s, o);
            if ((tid & 31) == 0) red[tid >> 5][i] = s;
        }
        __syncthreads();
        if (tid < NLAT) {
            float s = 0.f;
            #pragma unroll
            for (int w = 0; w < 8; w++) s += red[w][tid];
            g_part[chunk * (BATCH * NLAT) + b * NLAT + tid] = s;
        }
    } else {
        int j = (bid - ENC_BLOCKS) * 256 + tid;
        if (j >= N_FULL) return;
        float d[NLAT];
        #pragma unroll
        for (int i = 0; i < NLAT; i++) d[i] = dec[(size_t)i * N_FULL + j];
        g_dect[j * 4 + 0] = make_float4(d[0], d[1], d[2], d[3]);
        g_dect[j * 4 + 1] = make_float4(d[4], d[5], d[6], d[7]);
        g_dect[j * 4 + 2] = make_float4(d[8], d[9], 0.f, 0.f);
    }
}

// ---------------------------------------------------------------------------
// Kernel 2: main. Per block: TILE=16 nodes, 256 threads, 5 blocks/SM.
//   E: reduce encode partials (80 threads x 25 batched L2 loads + bias)
//   A: stage neighbour indices (coalesced)
//   B: cooperative gather — 3 lanes share one 64B decoder row (1 L1 line)
//   C: prefix sums over m via register-batched rounds (breaks LDS chain)
//   D: per (node,b,i-half): w=sigmoid(enc.bw) via __ldg; closed-form window
// ---------------------------------------------------------------------------
__global__ __launch_bounds__(256, 5)
void main_kernel(const float* __restrict__ bw,
                 const int*  __restrict__ nb,
                 const float* __restrict__ eb,
                 float*      __restrict__ out) {
    __shared__ float enc_s[BATCH * NLAT];
    __shared__ int   nbs[TILE * MU];          // 2KB; reused as float[256] for D-reduce
    __shared__ float P0s[TILE * NLAT * 33];   // [pl][i][m], stride 33
    __shared__ float P2s[TILE * NLAT * 33];

    int tid = threadIdx.x;
    int p0  = blockIdx.x * TILE;

    // ---- Phase E: per-block encode reduction (batched independent loads) ----
    if (tid < BATCH * NLAT) {
        float s = __ldg(&eb[tid - (tid / NLAT) * NLAT]);
        #pragma unroll
        for (int c = 0; c < ENC_CHUNKS; c++)
            s += g_part[c * (BATCH * NLAT) + tid];
        enc_s[tid] = s;
    }

    // ---- Phase A: stage indices (512 = 2 per thread) ----
    nbs[tid]       = __ldg(&nb[(size_t)p0 * MU + tid]);
    nbs[tid + 256] = __ldg(&nb[(size_t)p0 * MU + tid + 256]);
    __syncthreads();

    // ---- Phase B: cooperative gather (3 lanes per index -> 1 line) ----
    #pragma unroll
    for (int it = 0; it < TILE * MU * 3 / 256; it++) {
        int t = it * 256 + tid;
        int s = t / 3;                 // index id (0..511)
        int chunk = t - s * 3;         // 0,1,2
        int j = nbs[s];
        float4 v = g_dect[j * 4 + chunk];
        int base = (s >> 5) * (NLAT * 33) + (s & 31) + chunk * 132;
        P0s[base]      = v.x;
        P0s[base + 33] = v.y;
        if (chunk != 2) {
            P0s[base + 66] = v.z;
            P0s[base + 99] = v.w;
        }
    }
    __syncthreads();

    // ---- Phase C: prefix sums, register-batched in rounds of 8 ----
    if (tid < TILE * NLAT) {
        int base = tid * 33;
        float s0 = 0.f, s2 = 0.f;
        #pragma unroll
        for (int h = 0; h < 4; h++) {
            float g[8];
            #pragma unroll
            for (int q = 0; q < 8; q++) g[q] = P0s[base + h * 8 + q];  // batched
            #pragma unroll
            for (int q = 0; q < 8; q++) {
                int m = h * 8 + q;
                s0 += g[q];
                s2 = fmaf(g[q], (float)(m * m), s2);
                P0s[base + m] = s0;
                P2s[base + m] = s2;
            }
        }
    }
    __syncthreads();

    // ---- Phase D: 256 threads = 16 nodes x 8 b x 2 i-halves ----
    float* redf = (float*)nbs;
    {
        int b    = tid & 7;
        int pl   = (tid >> 3) & 15;
        int half = tid >> 7;
        int p    = p0 + pl;
        float eb_[NLAT];
        #pragma unroll
        for (int k = 0; k < NLAT; k++) eb_[k] = enc_s[b * NLAT + k];

        const float* bwp = bw + (size_t)half * 5 * NLAT * N_FULL + p;
        float acc = 0.f;
        #pragma unroll
        for (int ii = 0; ii < 5; ii++) {
            int i = half * 5 + ii;
            float t = 0.f;
            #pragma unroll
            for (int k = 0; k < NLAT; k++)
                t = fmaf(eb_[k], __ldg(&bwp[(size_t)(ii * NLAT + k) * N_FULL]), t);
            float w = 1.f / (1.f + __expf(-t));
            float u = fmaxf(32.f * w, 1e-6f);      // 32*w (window cutoff)
            float cinv = __fdividef(1.f, u * u);   // 1/(32w)^2
            int K = min(MU, (int)u + 1);           // #window terms
            float S2K = (float)((K - 1) * K * (2 * K - 1)) * (1.f / 6.f);
            int idx = (pl * NLAT + i) * 33 + (K - 1);
            float P0 = P0s[idx];
            float P2 = P2s[idx];
            float norm = (float)K - cinv * S2K;
            float sm = __fdividef(P0 - cinv * P2, norm);
            acc = fmaf(eb_[i], sm, acc);
        }
        redf[tid] = acc;
    }
    __syncthreads();
    if (tid < 128) {
        int b  = tid & 7;
        int pl = tid >> 3;
        out[(size_t)b * N_FULL + p0 + pl] = redf[tid] + redf[tid + 128];
    }
}

// ---------------------------------------------------------------------------
extern "C" void kernel_launch(void* const* d_in, const int* in_sizes, int n_in,
                              void* d_out, int out_size) {
    const float* x   = (const float*)d_in[0];
    const float* ew  = (const float*)d_in[1];
    const float* ebv = (const float*)d_in[2];
    const float* dec = (const float*)d_in[3];
    const float* bw  = (const float*)d_in[4];
    const int*   nb  = (const int*)d_in[5];
    float* out = (float*)d_out;

    encprep_kernel<<<ENC_BLOCKS + PREP_BLOCKS, 256>>>(x, ew, dec);
    main_kernel<<<N_FULL / TILE, 256>>>(bw, nb, ebv, out);
}